// round 10
// baseline (speedup 1.0000x reference)
#include <cuda_runtime.h>
#include <cuda_fp16.h>

// Problem constants (fixed by the reference)
#define VV   4096                 // vocab
#define MM   4                    // markov order
#define BB   8
#define LL   2048
#define FAN  (MM * (VV + 1))      // 16388
#define NPOS (BB * LL)            // 16384

#define VC   1024                 // vocab chunk; slab = FAN*VC*2B = 33.5 MB (L2-resident)
#define NCH  (VV / VC)            // 4 chunks

#define NSUB 4                    // subtiles per transpose block (along fan_in)
#define CT   (NSUB * 32)          // 128 fan_in columns per block
#define CMAIN 16384               // fan_in covered by main transpose tiles

// ONE slab, reused across all 4 chunks. Interleaved T(c)/G(c) launches keep it
// L2-resident: transpose writes re-dirty resident lines (no DRAM), gather
// reads hit L2. Only the final version ever writes back (~33 MB, lazy).
__device__ __half g_slab[(size_t)FAN * VC];

// ---------------------------------------------------------------------------
// Kernel 1: per-chunk transpose. W rows [v0, v0+VC) x all FAN cols
//   -> g_slab [FAN][VC] fp16.
// Proven 4x 32x33 scalar-smem subtile scheme (conflict-free both phases).
// W reads use __ldcs (evict-first streaming) to protect the slab in L2.
// grid = (CMAIN/CT + 1 = 129, VC/32 = 32), block (8,32).
// blockIdx.x == 128 handles the 4 remainder fan rows (16384..16387).
// ---------------------------------------------------------------------------
__global__ __launch_bounds__(256)
void ngram_transpose_chunk(const float* __restrict__ W, int v0) {
    const int tx = threadIdx.x;       // 0..7
    const int ty = threadIdx.y;       // 0..31

    if (blockIdx.x == CMAIN / CT) {
        // Remainder rows cc = 16384..16387 for this 32-vocab slice.
        const int t = ty * 8 + tx;    // 0..255
        if (t < 4 * 32) {
            const int r  = t >> 5;    // 0..3
            const int v  = t & 31;    // 0..31
            const int vl = blockIdx.y * 32 + v;       // local vocab in chunk
            g_slab[(size_t)(CMAIN + r) * VC + vl] =
                __float2half_rn(W[(size_t)(v0 + vl) * FAN + CMAIN + r]);
        }
        return;
    }

    __shared__ float tile[NSUB][32][33];

    const int c0  = blockIdx.x * CT;       // fan_in origin
    const int vl0 = blockIdx.y * 32;       // local vocab origin within chunk

    // Load phase: 4 independent float4 streaming reads, scalar smem writes.
    float4 w4[NSUB];
    const float4* wrow = reinterpret_cast<const float4*>(
        &W[(size_t)(v0 + vl0 + ty) * FAN + c0 + tx * 4]);
    #pragma unroll
    for (int s = 0; s < NSUB; s++)
        w4[s] = __ldcs(wrow + s * 8);      // evict-first: don't pollute L2
    #pragma unroll
    for (int s = 0; s < NSUB; s++) {
        tile[s][ty][tx * 4 + 0] = w4[s].x;
        tile[s][ty][tx * 4 + 1] = w4[s].y;
        tile[s][ty][tx * 4 + 2] = w4[s].z;
        tile[s][ty][tx * 4 + 3] = w4[s].w;
    }
    __syncthreads();

    // Store phase: scalar smem reads, cvt to fp16, 8-byte slab writes
    // (normal write-back stores -> allocate/re-dirty in L2).
    #pragma unroll
    for (int s = 0; s < NSUB; s++) {
        const int cc = c0 + s * 32 + ty;
        const __half2 p0 = __floats2half2_rn(tile[s][tx * 4 + 0][ty],
                                             tile[s][tx * 4 + 1][ty]);
        const __half2 p1 = __floats2half2_rn(tile[s][tx * 4 + 2][ty],
                                             tile[s][tx * 4 + 3][ty]);
        uint2 o;
        o.x = *reinterpret_cast<const unsigned int*>(&p0);
        o.y = *reinterpret_cast<const unsigned int*>(&p1);
        *reinterpret_cast<uint2*>(&g_slab[(size_t)cc * VC + vl0 + tx * 4]) = o;
    }
}

// ---------------------------------------------------------------------------
// Kernel 2: per-chunk gather-sum, warp-per-position, reading the L2-hot slab.
// grid = NPOS/8 = 2048, block = 256 (8 warps = 8 positions).
// Row pointers in registers; 4 iterations of 4 independent LDG.128 (slab,
// L2 hits) + 2 bias LDG (L2-resident) + cvt + 2 streaming STG.128.
// ---------------------------------------------------------------------------
__global__ __launch_bounds__(256, 4)
void ngram_gather_chunk(const int* __restrict__ idx,
                        const float* __restrict__ bias,
                        float* __restrict__ out, int v0) {
    const int warp = threadIdx.x >> 5;
    const int lane = threadIdx.x & 31;

    const int pos = blockIdx.x * 8 + warp;
    const int b   = pos >> 11;           // / LL
    const int l   = pos & (LL - 1);      // % LL

    const uint4* r0; const uint4* r1; const uint4* r2; const uint4* r3;
    {
        int tok;
        tok = (l >= 3) ? __ldg(&idx[b * LL + l - 3]) : VV;
        r0 = reinterpret_cast<const uint4*>(g_slab + (size_t)(0 * (VV + 1) + tok) * VC);
        tok = (l >= 2) ? __ldg(&idx[b * LL + l - 2]) : VV;
        r1 = reinterpret_cast<const uint4*>(g_slab + (size_t)(1 * (VV + 1) + tok) * VC);
        tok = (l >= 1) ? __ldg(&idx[b * LL + l - 1]) : VV;
        r2 = reinterpret_cast<const uint4*>(g_slab + (size_t)(2 * (VV + 1) + tok) * VC);
        tok = __ldg(&idx[b * LL + l]);
        r3 = reinterpret_cast<const uint4*>(g_slab + (size_t)(3 * (VV + 1) + tok) * VC);
    }

    const float4* b4 = reinterpret_cast<const float4*>(bias + v0);
    float4*       o4 = reinterpret_cast<float4*>(out + (size_t)pos * VV + v0);

    // VC/8 = 128 uint4 items per slab row / 32 lanes = 4 iterations.
    #pragma unroll
    for (int i = 0; i < VC / 8 / 32; i++) {
        const int j = lane + i * 32;

        const uint4 hs[4] = {r0[j], r1[j], r2[j], r3[j]};
        const float4 ba = b4[2 * j];
        const float4 bb = b4[2 * j + 1];

        float acc[8] = {ba.x, ba.y, ba.z, ba.w, bb.x, bb.y, bb.z, bb.w};
        #pragma unroll
        for (int k = 0; k < 4; k++) {
            const __half2* hp = reinterpret_cast<const __half2*>(&hs[k]);
            #pragma unroll
            for (int q = 0; q < 4; q++) {
                const float2 t = __half22float2(hp[q]);
                acc[2 * q + 0] += t.x;
                acc[2 * q + 1] += t.y;
            }
        }

        float4 oA, oB;
        oA.x = acc[0]; oA.y = acc[1]; oA.z = acc[2]; oA.w = acc[3];
        oB.x = acc[4]; oB.y = acc[5]; oB.z = acc[6]; oB.w = acc[7];
        __stcs(&o4[2 * j],     oA);     // streaming: don't evict the slab
        __stcs(&o4[2 * j + 1], oB);
    }
}

// ---------------------------------------------------------------------------
// Launch: interleaved T(c)/G(c) pairs so the slab round-trips through L2,
// never DRAM. Inputs identified by element count:
//   idx : B*L = 16384 (int32), bias : V = 4096, W : V*FAN (largest)
// ---------------------------------------------------------------------------
extern "C" void kernel_launch(void* const* d_in, const int* in_sizes, int n_in,
                              void* d_out, int out_size) {
    const int*   idx  = nullptr;
    const float* W    = nullptr;
    const float* bias = nullptr;

    for (int i = 0; i < n_in; i++) {
        if (in_sizes[i] == NPOS)      idx  = (const int*)d_in[i];
        else if (in_sizes[i] == VV)   bias = (const float*)d_in[i];
        else                          W    = (const float*)d_in[i];
    }

    dim3 tblock(8, 32);
    dim3 tgrid(CMAIN / CT + 1, VC / 32);      // (129, 32)

    for (int c = 0; c < NCH; c++) {
        ngram_transpose_chunk<<<tgrid, tblock>>>(W, c * VC);
        ngram_gather_chunk<<<NPOS / 8, 256>>>(idx, bias, (float*)d_out, c * VC);
    }
}